// round 16
// baseline (speedup 1.0000x reference)
#include <cuda_runtime.h>
#include <cuda_fp16.h>
#include <cstdint>
#include <math.h>

#define NROWS 8192
#define DIM   128
#define HID1  512
#define HID2  256
#define NUSERS 512

#define ROWB   144
#define CH32   (32 * ROWB)      // 4608
#define WSTGB  (128 * ROWB)     // 18432

// smem layout: 3 W buffers | A0/A2 union | A1 | SQP | RC
#define OFF_W    0
#define OFF_A02  (3 * WSTGB)              // 18432 (A0 = first 2 chunks; A2 = 4 chunks)
#define OFF_A1   (OFF_A02 + 4 * CH32)     // 36864
#define OFF_SQP  (OFF_A1 + 8 * CH32)      // 512
#define OFF_RC   (OFF_SQP + 512)          // 128
#define SMEM_TOTAL (OFF_RC + 128)         // 111232 -> 2 CTAs/SM

#define NCHUNKS 28

// ============ scratch ============
__device__ __align__(256) __half g_w1[HID1 * DIM];      // [512, 128]  (W1^T)
__device__ __align__(256) __half g_w2[HID2 * HID1];     // [256, 512]  (W2^T)
__device__ __align__(256) __half g_w3[DIM * HID2];      // [128, 256]  (W3^T)
__device__ __align__(256) float  g_pref[NROWS * DIM];   // prefix sums (ts-sorted buckets)
__device__ int g_cnt[NUSERS];     // zero at module load; re-zeroed by k_mlp tail
__device__ int g_fill[NUSERS];    // ditto
__device__ int g_off[NUSERS];
__device__ int g_idx[NROWS], g_tsb[NROWS];
__device__ int g_is64, g_clickbyte;

// ============================ helpers ============================
__device__ __forceinline__ uint32_t smem_to_u32(const void* p) {
    uint32_t a;
    asm("{ .reg .u64 t; cvta.to.shared.u64 t, %1; cvt.u32.u64 %0, t; }" : "=r"(a) : "l"(p));
    return a;
}
__device__ __forceinline__ void cp_async16(uint32_t smem, const void* gmem) {
    asm volatile("cp.async.cg.shared.global [%0], [%1], 16;" :: "r"(smem), "l"(gmem));
}
#define CP_COMMIT() asm volatile("cp.async.commit_group;" ::: "memory")
#define CP_WAIT(n)  asm volatile("cp.async.wait_group %0;" :: "n"(n) : "memory")

__device__ __forceinline__ void ldsm_x4(uint32_t r[4], uint32_t addr) {
    asm volatile("ldmatrix.sync.aligned.m8n8.x4.shared.b16 {%0,%1,%2,%3}, [%4];"
                 : "=r"(r[0]), "=r"(r[1]), "=r"(r[2]), "=r"(r[3]) : "r"(addr));
}
__device__ __forceinline__ void mma_fp16(float d[4], const uint32_t a[4], const uint32_t b[2]) {
    asm volatile(
        "mma.sync.aligned.m16n8k16.row.col.f32.f16.f16.f32 "
        "{%0,%1,%2,%3}, {%4,%5,%6,%7}, {%8,%9}, {%0,%1,%2,%3};"
        : "+f"(d[0]), "+f"(d[1]), "+f"(d[2]), "+f"(d[3])
        : "r"(a[0]), "r"(a[1]), "r"(a[2]), "r"(a[3]), "r"(b[0]), "r"(b[1]));
}
__device__ __forceinline__ int ld_user(const void* p, int j, int is64) {
    return is64 ? (int)((const long long*)p)[j] : ((const int*)p)[j];
}
__device__ __forceinline__ long long ld_ts(const void* p, int j, int is64) {
    return is64 ? ((const long long*)p)[j] : (long long)((const int*)p)[j];
}
__device__ __forceinline__ int ld_click(const void* p, int j, int cb) {
    return cb ? (((const unsigned char*)p)[j] != 0) : (((const int*)p)[j] != 0);
}
__device__ __forceinline__ void detect_local(const void* ts, const void* click,
                                             int tid, int nthr, int* s_flags,
                                             int& is64, int& cb) {
    if (tid == 0) { s_flags[0] = 0; s_flags[1] = 0; }
    __syncthreads();
    const unsigned int* tsw = (const unsigned int*)ts;
    unsigned int acc = 0;
    for (int i = tid; i < 2048; i += nthr) acc |= tsw[2 * i + 1];
    if (acc) atomicOr(&s_flags[0], 1);
    const unsigned int* cw = (const unsigned int*)click;
    int big = 0;
    for (int i = tid; i < 2048; i += nthr) if (cw[i] > 1u) big = 1;
    if (big) atomicOr(&s_flags[1], 1);
    __syncthreads();
    is64 = (s_flags[0] == 0) ? 1 : 0;
    cb = s_flags[1] ? 1 : 0;
}

// ============ K1: count clicks (blocks 0..15) + weight transpose (blocks 1..128) ============
__global__ void k_count_wt(const void* __restrict__ user, const void* __restrict__ ts,
                           const void* __restrict__ click,
                           const float* __restrict__ W1, const float* __restrict__ W2,
                           const float* __restrict__ W3) {
    __shared__ int s_flags[2];
    int t = threadIdx.x;
    int blk = blockIdx.x;

    if (blk < 16) {
        int is64, cb;
        detect_local(ts, click, t, 512, s_flags, is64, cb);
        if (blk == 0 && t == 0) { g_is64 = is64; g_clickbyte = cb; }
        int j = blk * 512 + t;
        if (ld_click(click, j, cb)) atomicAdd(&g_cnt[ld_user(user, j, is64)], 1);
    }
    if (blk >= 1) {
        int stride = 128 * 512;
        int tid = (blk - 1) * 512 + t;
        for (int i = tid; i < DIM * HID1; i += stride) {
            int k = i >> 9, n = i & 511;
            g_w1[n * DIM + k] = __float2half(W1[i]);
        }
        for (int i = tid; i < HID1 * HID2; i += stride) {
            int k = i >> 8, n = i & 255;
            g_w2[n * HID1 + k] = __float2half(W2[i]);
        }
        for (int i = tid; i < HID2 * DIM; i += stride) {
            int k = i >> 7, n = i & 127;
            g_w3[n * HID2 + k] = __float2half(W3[i]);
        }
    }
}

// ============ K2: scatter (each block re-derives offsets via local scan) ============
__global__ void k_scatter(const void* __restrict__ user, const void* __restrict__ ts,
                          const void* __restrict__ click) {
    __shared__ int off[NUSERS];
    int t = threadIdx.x;
    int is64 = g_is64, cb = g_clickbyte;
    int v = g_cnt[t];
    off[t] = v;
    __syncthreads();
    for (int o = 1; o < NUSERS; o <<= 1) {
        int x = (t >= o) ? off[t - o] : 0;
        __syncthreads();
        off[t] += x;
        __syncthreads();
    }
    off[t] -= v;
    if (blockIdx.x == 0) g_off[t] = off[t];
    __syncthreads();
    int j = blockIdx.x * 512 + t;
    if (ld_click(click, j, cb)) {
        int u = ld_user(user, j, is64);
        int pos = off[u] + atomicAdd(&g_fill[u], 1);
        g_idx[pos] = j;
        g_tsb[pos] = (int)ld_ts(ts, j, is64);
    }
}

// ============ K3: per-user (sort by ts, tie idx) + prefix sums of ad rows ============
__global__ void k_sortpref(const float* __restrict__ ad) {
    int u = blockIdx.x;
    int tid = threadIdx.x, lane = tid & 31;
    int b = g_off[u], n = g_cnt[u];
    if (n == 0) return;
    if (tid < 32 && n > 1) {
        if (n <= 32) {
            long long key = 0x7fffffffffffffffll;
            int j = 0, tsv = 0;
            if (lane < n) {
                j = g_idx[b + lane];
                tsv = g_tsb[b + lane];
                key = ((long long)tsv << 13) | (long long)j;
            }
            int rank = 0;
            #pragma unroll 1
            for (int l = 0; l < n; l++) {
                long long ok = __shfl_sync(0xffffffffu, key, l);
                if (lane < n && l != lane && ok < key) rank++;
            }
            __syncwarp();
            if (lane < n) { g_idx[b + rank] = j; g_tsb[b + rank] = tsv; }
        } else if (lane == 0) {
            for (int i = 1; i < n; i++) {
                int kj = g_idx[b + i], kt = g_tsb[b + i];
                long long kk = ((long long)kt << 13) | (long long)kj;
                int p = i - 1;
                while (p >= 0 &&
                       ((((long long)g_tsb[b + p]) << 13) | (long long)g_idx[b + p]) > kk) {
                    g_idx[b + p + 1] = g_idx[b + p];
                    g_tsb[b + p + 1] = g_tsb[b + p];
                    p--;
                }
                g_idx[b + p + 1] = kj;
                g_tsb[b + p + 1] = kt;
            }
        }
    }
    __syncthreads();
    float acc = 0.f;
    for (int k = 0; k < n; k++) {
        acc += ad[(size_t)g_idx[b + k] * DIM + tid];
        g_pref[(size_t)(b + k) * DIM + tid] = acc;
    }
}

// ============ flat W-chunk prefetch: fc in [0,28) -> (W matrix, bn, k0) ============
__device__ __forceinline__ void prefetch_chunk(uint32_t smem0, int fc, int tid) {
    const __half* W; int Kw, bnW, k0;
    if (fc < 8)       { W = g_w1; Kw = 128; bnW = (fc >> 1) * 128; k0 = (fc & 1) * 64; }
    else if (fc < 24) { int r = fc - 8;  W = g_w2; Kw = 512; bnW = (r >> 3) * 128; k0 = (r & 7) * 64; }
    else              { int r = fc - 24; W = g_w3; Kw = 256; bnW = 0; k0 = r * 64; }
    uint32_t sb = smem0 + (uint32_t)((fc % 3) * WSTGB);
    #pragma unroll
    for (int i = tid; i < 1024; i += 256) {
        int r = i >> 3, c = i & 7;
        cp_async16(sb + (uint32_t)(r * ROWB + c * 16),
                   W + (size_t)(bnW + r) * Kw + k0 + c * 8);
    }
    CP_COMMIT();
}

// ============ one pass: 32x128 tile over NCH chunks from the flat pipeline ============
template<int NCH, int PHASE>
__device__ __forceinline__ void mlp_pass(
    char* sm, uint32_t smem0, int& fc,
    uint32_t aBase, const float* __restrict__ bias, int bnW,
    uint32_t outBase, const int* rcnt_sm, float* __restrict__ outF, int bm)
{
    const int tid = threadIdx.x, wid = tid >> 5, lane = tid & 31;
    const int wm = wid & 1, wn = wid >> 1;
    const int lq = lane & 3, lr = lane >> 2;
    const uint32_t aOff = (uint32_t)((((lane >> 3) & 1) * 8 + (lane & 7)) * ROWB
                                     + (lane >> 4) * 16 + (wm * 16) * ROWB);
    const uint32_t bOff = (uint32_t)(((((lane >> 4) & 1) * 8) + (lane & 7)) * ROWB
                                     + ((lane >> 3) & 1) * 16 + (wn * 32) * ROWB);

    float d[4][4];
    #pragma unroll
    for (int nt = 0; nt < 4; nt++)
        #pragma unroll
        for (int q = 0; q < 4; q++) d[nt][q] = 0.f;

    #pragma unroll 1
    for (int ch = 0; ch < NCH; ch++) {
        if (fc == NCHUNKS - 1) { CP_WAIT(0); } else { CP_WAIT(1); }
        __syncthreads();   // chunk fc data visible; buffer (fc+2)%3 drained (read at fc-1)
        if (fc + 2 < NCHUNKS) prefetch_chunk(smem0, fc + 2, tid);
        uint32_t sA = aBase + (uint32_t)ch * CH32;
        uint32_t sB = smem0 + (uint32_t)((fc % 3) * WSTGB);
        #pragma unroll
        for (int ks = 0; ks < 4; ks++) {
            uint32_t Af[4], Bf[2][4];
            ldsm_x4(Af, sA + aOff + (uint32_t)(ks * 32));
            ldsm_x4(Bf[0], sB + bOff + (uint32_t)(ks * 32));
            ldsm_x4(Bf[1], sB + bOff + (uint32_t)(16 * ROWB + ks * 32));
            #pragma unroll
            for (int nt = 0; nt < 4; nt++)
                mma_fp16(d[nt], Af, &Bf[nt >> 1][(nt & 1) * 2]);
        }
        fc++;
    }

    if (PHASE == 0) {
        // bias + SiLU -> fp16 SMEM store (chunk layout); next pass's sync orders reads
        #pragma unroll
        for (int nt = 0; nt < 4; nt++) {
            int col = wn * 32 + nt * 8 + lq * 2;
            int gcol = bnW + col;
            float2 bb = *(const float2*)&bias[gcol];
            #pragma unroll
            for (int h = 0; h < 2; h++) {
                int row = wm * 16 + lr + h * 8;
                float x0 = d[nt][2 * h + 0] + bb.x;
                float x1 = d[nt][2 * h + 1] + bb.y;
                float s0 = x0 / (1.f + __expf(-x0));
                float s1 = x1 / (1.f + __expf(-x1));
                __half2 p = __floats2half2_rn(s0, s1);
                uint32_t addr = outBase + (uint32_t)((gcol >> 6) * CH32
                                                    + row * ROWB + (gcol & 63) * 2);
                asm volatile("st.shared.u32 [%0], %1;" :: "r"(addr), "r"(*(uint32_t*)&p));
            }
        }
    } else {
        float* sqp = (float*)(sm + OFF_SQP);
        if (tid < 128) sqp[tid] = 0.f;
        __syncthreads();
        #pragma unroll
        for (int h = 0; h < 2; h++) {
            float s = 0.f;
            #pragma unroll
            for (int nt = 0; nt < 4; nt++) {
                int col = wn * 32 + nt * 8 + lq * 2;
                float2 bb = *(const float2*)&bias[col];
                float e0 = d[nt][2 * h + 0] + bb.x;
                float e1 = d[nt][2 * h + 1] + bb.y;
                s += e0 * e0 + e1 * e1;
            }
            s += __shfl_xor_sync(0xffffffffu, s, 1);
            s += __shfl_xor_sync(0xffffffffu, s, 2);
            if (lq == 0) sqp[wn * 32 + wm * 16 + lr + h * 8] = s;
        }
        __syncthreads();
        #pragma unroll
        for (int h = 0; h < 2; h++) {
            int rl = wm * 16 + lr + h * 8;
            float S = sqp[rl] + sqp[32 + rl] + sqp[64 + rl] + sqp[96 + rl];
            float sc = 0.f;
            if (rcnt_sm[rl] > 0 && S > 0.f) sc = rsqrtf(S);
            #pragma unroll
            for (int nt = 0; nt < 4; nt++) {
                int col = wn * 32 + nt * 8 + lq * 2;
                float2 bb = *(const float2*)&bias[col];
                float2 v;
                v.x = (d[nt][2 * h + 0] + bb.x) * sc;
                v.y = (d[nt][2 * h + 1] + bb.y) * sc;
                *(float2*)&outF[(size_t)(bm + rl) * 128 + col] = v;
            }
        }
    }
}

// ============ fused hist + MLP: flat 28-chunk pipeline per 32-row stripe ============
__global__ __launch_bounds__(256, 2)
void k_mlp(const void* __restrict__ user, const void* __restrict__ ts,
           const float* __restrict__ b1, const float* __restrict__ b2,
           const float* __restrict__ b3,
           float* __restrict__ out)
{
    extern __shared__ char sm[];
    uint32_t smem0 = smem_to_u32(sm);
    const int tid = threadIdx.x;
    const int bm = blockIdx.x * 32;
    uint32_t A02 = smem0 + OFF_A02, A1 = smem0 + OFF_A1;
    int* rc_sm = (int*)(sm + OFF_RC);

    // start the W pipeline immediately (overlaps the history prologue)
    prefetch_chunk(smem0, 0, tid);
    prefetch_chunk(smem0, 1, tid);

    // ---- fused history prologue: compute A0 tile (32 rows) directly in SMEM ----
    {
        int r = tid >> 3;
        int d0 = (tid & 7) * 16;
        int is64 = g_is64;
        int gi = bm + r;
        int u = ld_user(user, gi, is64);
        long long ti = ld_ts(ts, gi, is64);
        int b = g_off[u], n = g_cnt[u];
        int lo = 0, hi = n;
        while (lo < hi) {
            int mid = (lo + hi) >> 1;
            if ((long long)g_tsb[b + mid] < ti) lo = mid + 1; else hi = mid;
        }
        int c = lo;
        float inv = c ? 1.f / (float)c : 0.f;
        const float* pr = &g_pref[(size_t)(b + (c > 0 ? c - 1 : 0)) * DIM];
        #pragma unroll
        for (int dd = 0; dd < 16; dd += 2) {
            int dim = d0 + dd;
            float v0 = c ? pr[dim] * inv : 0.f;
            float v1 = c ? pr[dim + 1] * inv : 0.f;
            __half2 p = __floats2half2_rn(v0, v1);
            uint32_t addr = A02 + (uint32_t)((dim >> 6) * CH32 + r * ROWB + (dim & 63) * 2);
            asm volatile("st.shared.u32 [%0], %1;" :: "r"(addr), "r"(*(uint32_t*)&p));
        }
        if ((tid & 7) == 0) rc_sm[r] = c;
    }
    // first chunk's CP_WAIT + __syncthreads orders these stores before A0 reads

    int fc = 0;
    // L1 (A0 in A02 region) -> A1
    mlp_pass<2, 0>(sm, smem0, fc, A02, b1, 0,   A1,  rc_sm, nullptr, bm);
    mlp_pass<2, 0>(sm, smem0, fc, A02, b1, 128, A1,  rc_sm, nullptr, bm);
    mlp_pass<2, 0>(sm, smem0, fc, A02, b1, 256, A1,  rc_sm, nullptr, bm);
    mlp_pass<2, 0>(sm, smem0, fc, A02, b1, 384, A1,  rc_sm, nullptr, bm);
    // L2: A1 -> A2 (A02 region; A0 dead)
    mlp_pass<8, 0>(sm, smem0, fc, A1,  b2, 0,   A02, rc_sm, nullptr, bm);
    mlp_pass<8, 0>(sm, smem0, fc, A1,  b2, 128, A02, rc_sm, nullptr, bm);
    // L3: A2 -> bias + L2norm + mask -> out
    mlp_pass<4, 1>(sm, smem0, fc, A02, b3, 0,   0,   rc_sm, out, bm);

    // reset counters for the next (graph-replayed) call
    if (blockIdx.x == 0 && tid < 256) {
        g_cnt[tid] = 0;  g_cnt[tid + 256] = 0;
        g_fill[tid] = 0; g_fill[tid + 256] = 0;
    }
}

// ============================ launch ============================
extern "C" void kernel_launch(void* const* d_in, const int* in_sizes, int n_in,
                              void* d_out, int out_size) {
    const float* ad    = (const float*)d_in[0];
    const void*  user  = d_in[1];
    const void*  ts    = d_in[2];
    const void*  click = d_in[3];
    const float* W1 = (const float*)d_in[4];
    const float* b1 = (const float*)d_in[5];
    const float* W2 = (const float*)d_in[6];
    const float* b2 = (const float*)d_in[7];
    const float* W3 = (const float*)d_in[8];
    const float* b3 = (const float*)d_in[9];
    float* out = (float*)d_out;

    cudaFuncSetAttribute(k_mlp, cudaFuncAttributeMaxDynamicSharedMemorySize, SMEM_TOTAL);

    k_count_wt<<<129, 512>>>(user, ts, click, W1, W2, W3);
    k_scatter<<<16, 512>>>(user, ts, click);
    k_sortpref<<<NUSERS, DIM>>>(ad);
    k_mlp<<<NROWS / 32, 256, SMEM_TOTAL>>>(user, ts, b1, b2, b3, out);
}

// round 17
// speedup vs baseline: 1.0050x; 1.0050x over previous
#include <cuda_runtime.h>
#include <cuda_fp16.h>
#include <cstdint>
#include <math.h>

#define NROWS 8192
#define DIM   128
#define HID1  512
#define HID2  256
#define NUSERS 512

#define ROWB   144
#define CH32   (32 * ROWB)      // 4608
#define WSTGB  (128 * ROWB)     // 18432

// smem layout: 3 W buffers | A0/A2 union | A1 | SQP | RC
#define OFF_W    0
#define OFF_A02  (3 * WSTGB)
#define OFF_A1   (OFF_A02 + 4 * CH32)
#define OFF_SQP  (OFF_A1 + 8 * CH32)      // 256 floats
#define OFF_RC   (OFF_SQP + 1024)
#define SMEM_TOTAL (OFF_RC + 128)         // 111744 -> 2 CTAs/SM

#define NCHUNKS 28
#define NTHR    512

// ============ scratch ============
__device__ __align__(256) __half g_w1[HID1 * DIM];      // [512, 128]  (W1^T)
__device__ __align__(256) __half g_w2[HID2 * HID1];     // [256, 512]  (W2^T)
__device__ __align__(256) __half g_w3[DIM * HID2];      // [128, 256]  (W3^T)
__device__ __align__(256) float  g_pref[NROWS * DIM];   // prefix sums (ts-sorted buckets)
__device__ int g_cnt[NUSERS];     // zero at module load; re-zeroed by k_mlp tail
__device__ int g_fill[NUSERS];    // ditto
__device__ int g_off[NUSERS];
__device__ int g_idx[NROWS], g_tsb[NROWS];
__device__ int g_is64, g_clickbyte;

// ============================ helpers ============================
__device__ __forceinline__ uint32_t smem_to_u32(const void* p) {
    uint32_t a;
    asm("{ .reg .u64 t; cvta.to.shared.u64 t, %1; cvt.u32.u64 %0, t; }" : "=r"(a) : "l"(p));
    return a;
}
__device__ __forceinline__ void cp_async16(uint32_t smem, const void* gmem) {
    asm volatile("cp.async.cg.shared.global [%0], [%1], 16;" :: "r"(smem), "l"(gmem));
}
#define CP_COMMIT() asm volatile("cp.async.commit_group;" ::: "memory")
#define CP_WAIT(n)  asm volatile("cp.async.wait_group %0;" :: "n"(n) : "memory")

__device__ __forceinline__ void ldsm_x4(uint32_t r[4], uint32_t addr) {
    asm volatile("ldmatrix.sync.aligned.m8n8.x4.shared.b16 {%0,%1,%2,%3}, [%4];"
                 : "=r"(r[0]), "=r"(r[1]), "=r"(r[2]), "=r"(r[3]) : "r"(addr));
}
__device__ __forceinline__ void mma_fp16(float d[4], const uint32_t a[4], const uint32_t b[2]) {
    asm volatile(
        "mma.sync.aligned.m16n8k16.row.col.f32.f16.f16.f32 "
        "{%0,%1,%2,%3}, {%4,%5,%6,%7}, {%8,%9}, {%0,%1,%2,%3};"
        : "+f"(d[0]), "+f"(d[1]), "+f"(d[2]), "+f"(d[3])
        : "r"(a[0]), "r"(a[1]), "r"(a[2]), "r"(a[3]), "r"(b[0]), "r"(b[1]));
}
__device__ __forceinline__ int ld_user(const void* p, int j, int is64) {
    return is64 ? (int)((const long long*)p)[j] : ((const int*)p)[j];
}
__device__ __forceinline__ long long ld_ts(const void* p, int j, int is64) {
    return is64 ? ((const long long*)p)[j] : (long long)((const int*)p)[j];
}
__device__ __forceinline__ int ld_click(const void* p, int j, int cb) {
    return cb ? (((const unsigned char*)p)[j] != 0) : (((const int*)p)[j] != 0);
}
__device__ __forceinline__ void detect_local(const void* ts, const void* click,
                                             int tid, int nthr, int* s_flags,
                                             int& is64, int& cb) {
    if (tid == 0) { s_flags[0] = 0; s_flags[1] = 0; }
    __syncthreads();
    const unsigned int* tsw = (const unsigned int*)ts;
    unsigned int acc = 0;
    for (int i = tid; i < 2048; i += nthr) acc |= tsw[2 * i + 1];
    if (acc) atomicOr(&s_flags[0], 1);
    const unsigned int* cw = (const unsigned int*)click;
    int big = 0;
    for (int i = tid; i < 2048; i += nthr) if (cw[i] > 1u) big = 1;
    if (big) atomicOr(&s_flags[1], 1);
    __syncthreads();
    is64 = (s_flags[0] == 0) ? 1 : 0;
    cb = s_flags[1] ? 1 : 0;
}

// ============ K1: count clicks (blocks 0..15) + weight transpose (blocks 1..128) ============
__global__ void k_count_wt(const void* __restrict__ user, const void* __restrict__ ts,
                           const void* __restrict__ click,
                           const float* __restrict__ W1, const float* __restrict__ W2,
                           const float* __restrict__ W3) {
    __shared__ int s_flags[2];
    int t = threadIdx.x;
    int blk = blockIdx.x;

    if (blk < 16) {
        int is64, cb;
        detect_local(ts, click, t, 512, s_flags, is64, cb);
        if (blk == 0 && t == 0) { g_is64 = is64; g_clickbyte = cb; }
        int j = blk * 512 + t;
        if (ld_click(click, j, cb)) atomicAdd(&g_cnt[ld_user(user, j, is64)], 1);
    }
    if (blk >= 1) {
        int stride = 128 * 512;
        int tid = (blk - 1) * 512 + t;
        for (int i = tid; i < DIM * HID1; i += stride) {
            int k = i >> 9, n = i & 511;
            g_w1[n * DIM + k] = __float2half(W1[i]);
        }
        for (int i = tid; i < HID1 * HID2; i += stride) {
            int k = i >> 8, n = i & 255;
            g_w2[n * HID1 + k] = __float2half(W2[i]);
        }
        for (int i = tid; i < HID2 * DIM; i += stride) {
            int k = i >> 7, n = i & 127;
            g_w3[n * HID2 + k] = __float2half(W3[i]);
        }
    }
}

// ============ K2: scatter (each block re-derives offsets via local scan) ============
__global__ void k_scatter(const void* __restrict__ user, const void* __restrict__ ts,
                          const void* __restrict__ click) {
    __shared__ int off[NUSERS];
    int t = threadIdx.x;
    int is64 = g_is64, cb = g_clickbyte;
    int v = g_cnt[t];
    off[t] = v;
    __syncthreads();
    for (int o = 1; o < NUSERS; o <<= 1) {
        int x = (t >= o) ? off[t - o] : 0;
        __syncthreads();
        off[t] += x;
        __syncthreads();
    }
    off[t] -= v;
    if (blockIdx.x == 0) g_off[t] = off[t];
    __syncthreads();
    int j = blockIdx.x * 512 + t;
    if (ld_click(click, j, cb)) {
        int u = ld_user(user, j, is64);
        int pos = off[u] + atomicAdd(&g_fill[u], 1);
        g_idx[pos] = j;
        g_tsb[pos] = (int)ld_ts(ts, j, is64);
    }
}

// ============ K3: per-user (sort by ts, tie idx) + prefix sums of ad rows ============
__global__ void k_sortpref(const float* __restrict__ ad) {
    int u = blockIdx.x;
    int tid = threadIdx.x, lane = tid & 31;
    int b = g_off[u], n = g_cnt[u];
    if (n == 0) return;
    if (tid < 32 && n > 1) {
        if (n <= 32) {
            long long key = 0x7fffffffffffffffll;
            int j = 0, tsv = 0;
            if (lane < n) {
                j = g_idx[b + lane];
                tsv = g_tsb[b + lane];
                key = ((long long)tsv << 13) | (long long)j;
            }
            int rank = 0;
            #pragma unroll 1
            for (int l = 0; l < n; l++) {
                long long ok = __shfl_sync(0xffffffffu, key, l);
                if (lane < n && l != lane && ok < key) rank++;
            }
            __syncwarp();
            if (lane < n) { g_idx[b + rank] = j; g_tsb[b + rank] = tsv; }
        } else if (lane == 0) {
            for (int i = 1; i < n; i++) {
                int kj = g_idx[b + i], kt = g_tsb[b + i];
                long long kk = ((long long)kt << 13) | (long long)kj;
                int p = i - 1;
                while (p >= 0 &&
                       ((((long long)g_tsb[b + p]) << 13) | (long long)g_idx[b + p]) > kk) {
                    g_idx[b + p + 1] = g_idx[b + p];
                    g_tsb[b + p + 1] = g_tsb[b + p];
                    p--;
                }
                g_idx[b + p + 1] = kj;
                g_tsb[b + p + 1] = kt;
            }
        }
    }
    __syncthreads();
    float acc = 0.f;
    for (int k = 0; k < n; k++) {
        acc += ad[(size_t)g_idx[b + k] * DIM + tid];
        g_pref[(size_t)(b + k) * DIM + tid] = acc;
    }
}

// ============ flat W-chunk prefetch ============
__device__ __forceinline__ void prefetch_chunk(uint32_t smem0, int fc, int tid) {
    const __half* W; int Kw, bnW, k0;
    if (fc < 8)       { W = g_w1; Kw = 128; bnW = (fc >> 1) * 128; k0 = (fc & 1) * 64; }
    else if (fc < 24) { int r = fc - 8;  W = g_w2; Kw = 512; bnW = (r >> 3) * 128; k0 = (r & 7) * 64; }
    else              { int r = fc - 24; W = g_w3; Kw = 256; bnW = 0; k0 = r * 64; }
    uint32_t sb = smem0 + (uint32_t)((fc % 3) * WSTGB);
    #pragma unroll
    for (int i = tid; i < 1024; i += NTHR) {
        int r = i >> 3, c = i & 7;
        cp_async16(sb + (uint32_t)(r * ROWB + c * 16),
                   W + (size_t)(bnW + r) * Kw + k0 + c * 8);
    }
    CP_COMMIT();
}

// ============ one pass: 32x128 tile; 16 warps = 2(m:16) x 8(n:16) ============
template<int NCH, int PHASE>
__device__ __forceinline__ void mlp_pass(
    char* sm, uint32_t smem0, int& fc,
    uint32_t aBase, const float* __restrict__ bias, int bnW,
    uint32_t outBase, const int* rcnt_sm, float* __restrict__ outF, int bm)
{
    const int tid = threadIdx.x, wid = tid >> 5, lane = tid & 31;
    const int wm = wid & 1, wn = wid >> 1;          // 2 m-warps x 8 n-warps
    const int lq = lane & 3, lr = lane >> 2;
    const uint32_t aOff = (uint32_t)((((lane >> 3) & 1) * 8 + (lane & 7)) * ROWB
                                     + (lane >> 4) * 16 + (wm * 16) * ROWB);
    const uint32_t bOff = (uint32_t)(((((lane >> 4) & 1) * 8) + (lane & 7)) * ROWB
                                     + ((lane >> 3) & 1) * 16 + (wn * 16) * ROWB);

    float d[2][4];
    #pragma unroll
    for (int nt = 0; nt < 2; nt++)
        #pragma unroll
        for (int q = 0; q < 4; q++) d[nt][q] = 0.f;

    #pragma unroll 1
    for (int ch = 0; ch < NCH; ch++) {
        if (fc == NCHUNKS - 1) { CP_WAIT(0); } else { CP_WAIT(1); }
        __syncthreads();
        if (fc + 2 < NCHUNKS) prefetch_chunk(smem0, fc + 2, tid);
        uint32_t sA = aBase + (uint32_t)ch * CH32;
        uint32_t sB = smem0 + (uint32_t)((fc % 3) * WSTGB);
        #pragma unroll
        for (int ks = 0; ks < 4; ks++) {
            uint32_t Af[4], Bf[4];
            ldsm_x4(Af, sA + aOff + (uint32_t)(ks * 32));
            ldsm_x4(Bf, sB + bOff + (uint32_t)(ks * 32));
            mma_fp16(d[0], Af, &Bf[0]);
            mma_fp16(d[1], Af, &Bf[2]);
        }
        fc++;
    }

    if (PHASE == 0) {
        // bias + SiLU -> fp16 SMEM store (chunk layout)
        #pragma unroll
        for (int nt = 0; nt < 2; nt++) {
            int col = wn * 16 + nt * 8 + lq * 2;
            int gcol = bnW + col;
            float2 bb = *(const float2*)&bias[gcol];
            #pragma unroll
            for (int h = 0; h < 2; h++) {
                int row = wm * 16 + lr + h * 8;
                float x0 = d[nt][2 * h + 0] + bb.x;
                float x1 = d[nt][2 * h + 1] + bb.y;
                float s0 = x0 / (1.f + __expf(-x0));
                float s1 = x1 / (1.f + __expf(-x1));
                __half2 p = __floats2half2_rn(s0, s1);
                uint32_t addr = outBase + (uint32_t)((gcol >> 6) * CH32
                                                    + row * ROWB + (gcol & 63) * 2);
                asm volatile("st.shared.u32 [%0], %1;" :: "r"(addr), "r"(*(uint32_t*)&p));
            }
        }
    } else {
        // bias + L2 norm + empty mask; reduce over 8 n-warps
        float* sqp = (float*)(sm + OFF_SQP);   // [8 n-warps][32 rows]
        if (tid < 256) sqp[tid] = 0.f;
        __syncthreads();
        #pragma unroll
        for (int h = 0; h < 2; h++) {
            float s = 0.f;
            #pragma unroll
            for (int nt = 0; nt < 2; nt++) {
                int col = wn * 16 + nt * 8 + lq * 2;
                float2 bb = *(const float2*)&bias[col];
                float e0 = d[nt][2 * h + 0] + bb.x;
                float e1 = d[nt][2 * h + 1] + bb.y;
                s += e0 * e0 + e1 * e1;
            }
            s += __shfl_xor_sync(0xffffffffu, s, 1);
            s += __shfl_xor_sync(0xffffffffu, s, 2);
            if (lq == 0) sqp[wn * 32 + wm * 16 + lr + h * 8] = s;
        }
        __syncthreads();
        #pragma unroll
        for (int h = 0; h < 2; h++) {
            int rl = wm * 16 + lr + h * 8;
            float S = 0.f;
            #pragma unroll
            for (int w = 0; w < 8; w++) S += sqp[w * 32 + rl];
            float sc = 0.f;
            if (rcnt_sm[rl] > 0 && S > 0.f) sc = rsqrtf(S);
            #pragma unroll
            for (int nt = 0; nt < 2; nt++) {
                int col = wn * 16 + nt * 8 + lq * 2;
                float2 bb = *(const float2*)&bias[col];
                float2 v;
                v.x = (d[nt][2 * h + 0] + bb.x) * sc;
                v.y = (d[nt][2 * h + 1] + bb.y) * sc;
                *(float2*)&outF[(size_t)(bm + rl) * 128 + col] = v;
            }
        }
    }
}

// ============ fused hist + MLP: flat 28-chunk pipeline per 32-row stripe ============
__global__ __launch_bounds__(NTHR, 2)
void k_mlp(const void* __restrict__ user, const void* __restrict__ ts,
           const float* __restrict__ b1, const float* __restrict__ b2,
           const float* __restrict__ b3,
           float* __restrict__ out)
{
    extern __shared__ char sm[];
    uint32_t smem0 = smem_to_u32(sm);
    const int tid = threadIdx.x;
    const int bm = blockIdx.x * 32;
    uint32_t A02 = smem0 + OFF_A02, A1 = smem0 + OFF_A1;
    int* rc_sm = (int*)(sm + OFF_RC);

    // start the W pipeline immediately (overlaps the history prologue)
    prefetch_chunk(smem0, 0, tid);
    prefetch_chunk(smem0, 1, tid);

    // ---- fused history prologue: A0 tile (32 rows) directly in SMEM ----
    {
        int r = tid >> 4;              // 0..31
        int d0 = (tid & 15) * 8;       // 8 dims per thread
        int is64 = g_is64;
        int gi = bm + r;
        int u = ld_user(user, gi, is64);
        long long ti = ld_ts(ts, gi, is64);
        int b = g_off[u], n = g_cnt[u];
        int lo = 0, hi = n;
        while (lo < hi) {
            int mid = (lo + hi) >> 1;
            if ((long long)g_tsb[b + mid] < ti) lo = mid + 1; else hi = mid;
        }
        int c = lo;
        float inv = c ? 1.f / (float)c : 0.f;
        const float* pr = &g_pref[(size_t)(b + (c > 0 ? c - 1 : 0)) * DIM];
        #pragma unroll
        for (int dd = 0; dd < 8; dd += 2) {
            int dim = d0 + dd;
            float v0 = c ? pr[dim] * inv : 0.f;
            float v1 = c ? pr[dim + 1] * inv : 0.f;
            __half2 p = __floats2half2_rn(v0, v1);
            uint32_t addr = A02 + (uint32_t)((dim >> 6) * CH32 + r * ROWB + (dim & 63) * 2);
            asm volatile("st.shared.u32 [%0], %1;" :: "r"(addr), "r"(*(uint32_t*)&p));
        }
        if ((tid & 15) == 0) rc_sm[r] = c;
    }
    // first chunk's CP_WAIT + __syncthreads orders these stores before A0 reads

    int fc = 0;
    mlp_pass<2, 0>(sm, smem0, fc, A02, b1, 0,   A1,  rc_sm, nullptr, bm);
    mlp_pass<2, 0>(sm, smem0, fc, A02, b1, 128, A1,  rc_sm, nullptr, bm);
    mlp_pass<2, 0>(sm, smem0, fc, A02, b1, 256, A1,  rc_sm, nullptr, bm);
    mlp_pass<2, 0>(sm, smem0, fc, A02, b1, 384, A1,  rc_sm, nullptr, bm);
    mlp_pass<8, 0>(sm, smem0, fc, A1,  b2, 0,   A02, rc_sm, nullptr, bm);
    mlp_pass<8, 0>(sm, smem0, fc, A1,  b2, 128, A02, rc_sm, nullptr, bm);
    mlp_pass<4, 1>(sm, smem0, fc, A02, b3, 0,   0,   rc_sm, out, bm);

    // reset counters for the next (graph-replayed) call
    if (blockIdx.x == 0 && tid < 256) {
        g_cnt[tid] = 0;  g_cnt[tid + 256] = 0;
        g_fill[tid] = 0; g_fill[tid + 256] = 0;
    }
}

// ============================ launch ============================
extern "C" void kernel_launch(void* const* d_in, const int* in_sizes, int n_in,
                              void* d_out, int out_size) {
    const float* ad    = (const float*)d_in[0];
    const void*  user  = d_in[1];
    const void*  ts    = d_in[2];
    const void*  click = d_in[3];
    const float* W1 = (const float*)d_in[4];
    const float* b1 = (const float*)d_in[5];
    const float* W2 = (const float*)d_in[6];
    const float* b2 = (const float*)d_in[7];
    const float* W3 = (const float*)d_in[8];
    const float* b3 = (const float*)d_in[9];
    float* out = (float*)d_out;

    cudaFuncSetAttribute(k_mlp, cudaFuncAttributeMaxDynamicSharedMemorySize, SMEM_TOTAL);

    k_count_wt<<<129, 512>>>(user, ts, click, W1, W2, W3);
    k_scatter<<<16, 512>>>(user, ts, click);
    k_sortpref<<<NUSERS, DIM>>>(ad);
    k_mlp<<<NROWS / 32, NTHR, SMEM_TOTAL>>>(user, ts, b1, b2, b3, out);
}